// round 6
// baseline (speedup 1.0000x reference)
#include <cuda_runtime.h>

// Problem constants (fixed by the reference)
#define BATCH  8
#define NNODE  20000
#define CDIM   256
#define NEDGE  320000

// ---------------- device scratch (allocation-free rule: __device__ globals) ---------
__device__ int   g_hi_nonzero;          // 1 => edge_index buffer is int32
__device__ int   g_deg[NNODE];
__device__ int   g_cnt[NNODE];          // in-degree (dst histogram) for CSR
__device__ int   g_cursor[NNODE];
__device__ float g_dis[NNODE];
__device__ int   g_rowptr[NNODE + 1];
__device__ int   g_csr_src[NEDGE];
__device__ float g_csr_w[NEDGE];
__device__ float g_Tx1[(size_t)BATCH * NNODE * CDIM];   // 163.8 MB
__device__ float g_P2 [(size_t)BATCH * NNODE * CDIM];   // 163.8 MB
__device__ float g_Wc [3 * CDIM * CDIM];                // folded [768,256] weight

// ---------------- dtype detection ---------------------------------------------------
// Node indices are < 20000, so int64 storage has zero high words everywhere.
// If the buffer is int32, word (2t+1) is a random index (nonzero w.p. 19999/20000).
__global__ void k_detect(const int* __restrict__ p32) {
    int t = threadIdx.x;                     // 0..255 -> safe: 512 ints = min buffer size
    if (p32[2 * t + 1] != 0) atomicOr(&g_hi_nonzero, 1);
}

__device__ __forceinline__ void load_edge(const int* __restrict__ p, int e, int& s, int& d) {
    if (g_hi_nonzero) {                      // int32 layout: [2, E] contiguous
        s = p[e];
        d = p[NEDGE + e];
    } else {                                 // int64 little-endian: low word at 2*idx
        s = p[2 * e];
        d = p[2 * (NEDGE + e)];
    }
}

// ---------------- graph prep kernels ------------------------------------------------
__global__ void k_zero() {
    int i = blockIdx.x * blockDim.x + threadIdx.x;
    if (i < NNODE) { g_deg[i] = 0; g_cnt[i] = 0; g_cursor[i] = 0; }
    if (i == 0) g_hi_nonzero = 0;
}

__global__ void k_deg(const int* __restrict__ ei) {
    int e = blockIdx.x * blockDim.x + threadIdx.x;
    if (e < NEDGE) {
        int s, d;
        load_edge(ei, e, s, d);
        atomicAdd(&g_deg[s], 1);
        atomicAdd(&g_cnt[d], 1);
    }
}

__global__ void k_dis() {
    int i = blockIdx.x * blockDim.x + threadIdx.x;
    if (i < NNODE) {
        int d = g_deg[i];
        g_dis[i] = (d > 0) ? rsqrtf((float)d) : 0.0f;
    }
}

// single-block exclusive scan of g_cnt -> g_rowptr (N=20000)
__global__ void k_scan() {
    __shared__ int sh[1024];
    const int CH = 20;                      // 1024*20 = 20480 >= 20000
    int t = threadIdx.x;
    int base = t * CH;
    int sum = 0;
    for (int i = 0; i < CH; i++) {
        int idx = base + i;
        if (idx < NNODE) sum += g_cnt[idx];
    }
    sh[t] = sum;
    __syncthreads();
    for (int o = 1; o < 1024; o <<= 1) {
        int v = (t >= o) ? sh[t - o] : 0;
        __syncthreads();
        sh[t] += v;
        __syncthreads();
    }
    int run = sh[t] - sum;                  // exclusive prefix for this thread
    for (int i = 0; i < CH; i++) {
        int idx = base + i;
        if (idx < NNODE) { g_rowptr[idx] = run; run += g_cnt[idx]; }
    }
    if (t == 1023) g_rowptr[NNODE] = sh[1023];
}

__global__ void k_fill(const int* __restrict__ ei) {
    int e = blockIdx.x * blockDim.x + threadIdx.x;
    if (e < NEDGE) {
        int s, d;
        load_edge(ei, e, s, d);
        float w = -g_dis[s] * g_dis[d];
        int pos = atomicAdd(&g_cursor[d], 1);
        int idx = g_rowptr[d] + pos;
        g_csr_src[idx] = s;
        g_csr_w[idx]   = w;
    }
}

// fold layer-1 weights: Wc = [W0-W2 ; W1 ; 2*W2]  (since Tx2 = 2*P2 - Tx0)
__global__ void k_wc(const float* __restrict__ W) {
    int idx = blockIdx.x * blockDim.x + threadIdx.x;   // < 3*256*256
    const int CC = CDIM * CDIM;
    int seg = idx / CC;
    int r   = idx - seg * CC;
    const float* Wl = W + 1 * 3 * CC;                  // layer 1
    float v;
    if      (seg == 0) v = Wl[0 * CC + r] - Wl[2 * CC + r];
    else if (seg == 1) v = Wl[1 * CC + r];
    else               v = 2.0f * Wl[2 * CC + r];
    g_Wc[idx] = v;
}

// ---------------- propagation: Y[b,v,:] = sum_e norm[e] * X[b,src[e],:] ------------
// phase 0: X = feats (param), Y = g_Tx1 ;  phase 1: X = g_Tx1, Y = g_P2
__global__ void k_prop(const float* __restrict__ Xext, int phase) {
    const float* X = (phase == 0) ? Xext : (const float*)g_Tx1;
    float*       Y = (phase == 0) ? g_Tx1 : g_P2;

    int v = blockIdx.x;
    int b = blockIdx.y;
    int t = threadIdx.x;                   // 0..63, each owns float4 of channels

    __shared__ int   ss[64];
    __shared__ float sw[64];

    int start = g_rowptr[v];
    int end   = g_rowptr[v + 1];

    const float4* X4 = (const float4*)X + (size_t)b * NNODE * (CDIM / 4);
    float4 acc = make_float4(0.f, 0.f, 0.f, 0.f);

    for (int e0 = start; e0 < end; e0 += 64) {
        int ne = min(64, end - e0);
        if (t < ne) { ss[t] = g_csr_src[e0 + t]; sw[t] = g_csr_w[e0 + t]; }
        __syncthreads();
        #pragma unroll 4
        for (int i = 0; i < ne; i++) {
            float  w = sw[i];
            float4 x = X4[(size_t)ss[i] * (CDIM / 4) + t];
            acc.x += w * x.x; acc.y += w * x.y;
            acc.z += w * x.z; acc.w += w * x.w;
        }
        __syncthreads();
    }
    ((float4*)Y)[((size_t)b * NNODE + v) * (CDIM / 4) + t] = acc;
}

// ---------------- GEMM + bias + LayerNorm fused ------------------------------------
// out[160000,256] = [feats|Tx1|P2](M x 768) @ Wc(768 x 256) + b, then row LayerNorm.
// BM=64, BN=256 (full row -> LN in-block), BK=16, 256 thr, 8x8 microtile.
__global__ void __launch_bounds__(256, 2)
k_gemm(const float* __restrict__ A0,
       const float* __restrict__ bias,
       const float* __restrict__ lnw,
       const float* __restrict__ lnb,
       float* __restrict__ out)
{
    __shared__ float As[16][65];      // [k][m], padded
    __shared__ float Bs[16][256];     // [k][n]

    int tid = threadIdx.x;
    int ty = tid >> 5;                // warp id 0..7 -> rows [ty*8, ty*8+8)
    int tx = tid & 31;                // lane -> cols {j*32+tx}
    int m0 = blockIdx.x * 64;

    float acc[8][8];
    #pragma unroll
    for (int i = 0; i < 8; i++)
        #pragma unroll
        for (int j = 0; j < 8; j++) acc[i][j] = 0.0f;

    int lm = tid >> 2;                // A row within tile (0..63)
    int lk = (tid & 3) * 4;           // A k offset (0,4,8,12)
    int bk = tid >> 4;                // B k row (0..15)
    int bn = (tid & 15) * 16;         // B col base

    for (int kt = 0; kt < 48; kt++) {
        int seg = kt >> 4;            // 0:feats 1:Tx1 2:P2
        const float* Aseg = (seg == 0) ? A0
                           : (seg == 1) ? (const float*)g_Tx1
                                        : (const float*)g_P2;
        int kl = (kt & 15) * 16;

        float4 av = *(const float4*)(Aseg + (size_t)(m0 + lm) * CDIM + kl + lk);
        As[lk + 0][lm] = av.x; As[lk + 1][lm] = av.y;
        As[lk + 2][lm] = av.z; As[lk + 3][lm] = av.w;

        const float4* Bg = (const float4*)(g_Wc + (size_t)(kt * 16 + bk) * CDIM + bn);
        float4 b0 = Bg[0], b1 = Bg[1], b2 = Bg[2], b3 = Bg[3];
        *(float4*)&Bs[bk][bn + 0]  = b0;
        *(float4*)&Bs[bk][bn + 4]  = b1;
        *(float4*)&Bs[bk][bn + 8]  = b2;
        *(float4*)&Bs[bk][bn + 12] = b3;

        __syncthreads();
        #pragma unroll
        for (int kk = 0; kk < 16; kk++) {
            float ra[8], rb[8];
            #pragma unroll
            for (int i = 0; i < 8; i++) ra[i] = As[kk][ty * 8 + i];
            #pragma unroll
            for (int j = 0; j < 8; j++) rb[j] = Bs[kk][j * 32 + tx];
            #pragma unroll
            for (int i = 0; i < 8; i++)
                #pragma unroll
                for (int j = 0; j < 8; j++)
                    acc[i][j] += ra[i] * rb[j];
        }
        __syncthreads();
    }

    // epilogue: + bias, LayerNorm over 256 channels (warp-wide shuffles), affine, store
    float bb[8], lw[8], lb[8];
    #pragma unroll
    for (int j = 0; j < 8; j++) {
        int col = j * 32 + tx;
        bb[j] = bias[col]; lw[j] = lnw[col]; lb[j] = lnb[col];
    }

    #pragma unroll
    for (int i = 0; i < 8; i++) {
        float v[8];
        float s = 0.0f;
        #pragma unroll
        for (int j = 0; j < 8; j++) { v[j] = acc[i][j] + bb[j]; s += v[j]; }
        #pragma unroll
        for (int o = 16; o > 0; o >>= 1) s += __shfl_xor_sync(0xffffffffu, s, o);
        float mu = s * (1.0f / CDIM);
        float s2 = 0.0f;
        #pragma unroll
        for (int j = 0; j < 8; j++) { float d = v[j] - mu; s2 += d * d; }
        #pragma unroll
        for (int o = 16; o > 0; o >>= 1) s2 += __shfl_xor_sync(0xffffffffu, s2, o);
        float inv = rsqrtf(s2 * (1.0f / CDIM) + 1e-5f);

        size_t row = (size_t)m0 + ty * 8 + i;
        #pragma unroll
        for (int j = 0; j < 8; j++)
            out[row * CDIM + j * 32 + tx] = (v[j] - mu) * inv * lw[j] + lb[j];
    }
}

// ---------------- launch -------------------------------------------------------------
extern "C" void kernel_launch(void* const* d_in, const int* in_sizes, int n_in,
                              void* d_out, int out_size) {
    const float* feats = (const float*)d_in[0];      // [B*N, C]
    const float* W     = (const float*)d_in[1];      // [L,K,C,C]
    const float* bpar  = (const float*)d_in[2];      // [L,C]
    const float* lnw   = (const float*)d_in[3];      // [L,C]
    const float* lnb   = (const float*)d_in[4];      // [L,C]
    const int*   ei    = (const int*)d_in[5];        // [2,E] int32 OR int64 (detected)
    float* out = (float*)d_out;

    k_zero  <<<(NNODE + 255) / 256, 256>>>();
    k_detect<<<1, 256>>>(ei);
    k_deg   <<<(NEDGE + 255) / 256, 256>>>(ei);
    k_dis   <<<(NNODE + 255) / 256, 256>>>();
    k_scan  <<<1, 1024>>>();
    k_fill  <<<(NEDGE + 255) / 256, 256>>>(ei);
    k_wc    <<<(3 * CDIM * CDIM) / 256, 256>>>(W);

    k_prop<<<dim3(NNODE, BATCH), 64>>>(feats, 0);   // Tx1 = A_hat @ feats
    k_prop<<<dim3(NNODE, BATCH), 64>>>(nullptr, 1); // P2  = A_hat @ Tx1

    // only layer 1 survives in the reference -> use its params
    k_gemm<<<(BATCH * NNODE) / 64, 256>>>(feats, bpar + CDIM, lnw + CDIM, lnb + CDIM, out);
}

// round 9
// speedup vs baseline: 2.6550x; 2.6550x over previous
#include <cuda_runtime.h>
#include <cuda_bf16.h>
#include <cstdint>

// Problem constants (fixed by the reference)
#define BATCH  8
#define NNODE  20000
#define CDIM   256
#define NEDGE  320000

// ---------------- device scratch (allocation-free rule: __device__ globals) ---------
__device__ int   g_hi_nonzero;          // 1 => edge_index buffer is int32
__device__ int   g_deg[NNODE];
__device__ int   g_cnt[NNODE];
__device__ int   g_cursor[NNODE];
__device__ float g_dis[NNODE];
__device__ int   g_rowptr[NNODE + 1];
__device__ int   g_csr_src[NEDGE];
__device__ float g_csr_w[NEDGE];
__device__ float g_Tx1[(size_t)BATCH * NNODE * CDIM];   // 163.8 MB
__device__ float g_P2 [(size_t)BATCH * NNODE * CDIM];   // 163.8 MB
// folded layer-1 weights, bf16 split precision, [K=768][N=256] row-major
__device__ __nv_bfloat16 g_W_hi[768 * 256];
__device__ __nv_bfloat16 g_W_lo[768 * 256];

// ---------------- dtype detection ---------------------------------------------------
// Node indices < 20000 -> int64 storage has zero high words everywhere.
__global__ void k_detect(const int* __restrict__ p32) {
    int t = threadIdx.x;
    if (p32[2 * t + 1] != 0) atomicOr(&g_hi_nonzero, 1);
}
__device__ __forceinline__ void load_edge(const int* __restrict__ p, int e, int& s, int& d) {
    if (g_hi_nonzero) { s = p[e];      d = p[NEDGE + e]; }
    else              { s = p[2 * e];  d = p[2 * (NEDGE + e)]; }
}

// ---------------- graph prep kernels ------------------------------------------------
__global__ void k_zero() {
    int i = blockIdx.x * blockDim.x + threadIdx.x;
    if (i < NNODE) { g_deg[i] = 0; g_cnt[i] = 0; g_cursor[i] = 0; }
    if (i == 0) g_hi_nonzero = 0;
}
__global__ void k_deg(const int* __restrict__ ei) {
    int e = blockIdx.x * blockDim.x + threadIdx.x;
    if (e < NEDGE) {
        int s, d; load_edge(ei, e, s, d);
        atomicAdd(&g_deg[s], 1);
        atomicAdd(&g_cnt[d], 1);
    }
}
__global__ void k_dis() {
    int i = blockIdx.x * blockDim.x + threadIdx.x;
    if (i < NNODE) {
        int d = g_deg[i];
        g_dis[i] = (d > 0) ? rsqrtf((float)d) : 0.0f;
    }
}
__global__ void k_scan() {
    __shared__ int sh[1024];
    const int CH = 20;
    int t = threadIdx.x;
    int base = t * CH;
    int sum = 0;
    for (int i = 0; i < CH; i++) { int idx = base + i; if (idx < NNODE) sum += g_cnt[idx]; }
    sh[t] = sum;
    __syncthreads();
    for (int o = 1; o < 1024; o <<= 1) {
        int v = (t >= o) ? sh[t - o] : 0;
        __syncthreads();
        sh[t] += v;
        __syncthreads();
    }
    int run = sh[t] - sum;
    for (int i = 0; i < CH; i++) {
        int idx = base + i;
        if (idx < NNODE) { g_rowptr[idx] = run; run += g_cnt[idx]; }
    }
    if (t == 1023) g_rowptr[NNODE] = sh[1023];
}
__global__ void k_fill(const int* __restrict__ ei) {
    int e = blockIdx.x * blockDim.x + threadIdx.x;
    if (e < NEDGE) {
        int s, d; load_edge(ei, e, s, d);
        float w = -g_dis[s] * g_dis[d];
        int pos = atomicAdd(&g_cursor[d], 1);
        int idx = g_rowptr[d] + pos;
        g_csr_src[idx] = s;
        g_csr_w[idx]   = w;
    }
}

// fold layer-1 weights into bf16 hi/lo, [K=768][N=256]:
// Wc = [W0-W2 ; W1 ; 2*W2]  (since Tx2 = 2*P2 - Tx0)
__global__ void k_wc(const float* __restrict__ W) {
    int idx = blockIdx.x * blockDim.x + threadIdx.x;   // < 3*256*256, = kg*256 + n
    const int CC = CDIM * CDIM;
    int seg = idx / CC;
    int r   = idx - seg * CC;
    const float* Wl = W + 1 * 3 * CC;  // layer 1
    float v;
    if      (seg == 0) v = Wl[r] - Wl[2 * CC + r];
    else if (seg == 1) v = Wl[CC + r];
    else               v = 2.0f * Wl[2 * CC + r];
    __nv_bfloat16 h = __float2bfloat16(v);
    float lo = v - __bfloat162float(h);
    g_W_hi[idx] = h;
    g_W_lo[idx] = __float2bfloat16(lo);
}

// ---------------- propagation (unchanged from passing R6 kernel) --------------------
__global__ void k_prop(const float* __restrict__ Xext, int phase) {
    const float* X = (phase == 0) ? Xext : (const float*)g_Tx1;
    float*       Y = (phase == 0) ? g_Tx1 : g_P2;

    int v = blockIdx.x;
    int b = blockIdx.y;
    int t = threadIdx.x;

    __shared__ int   ss[64];
    __shared__ float sw[64];

    int start = g_rowptr[v];
    int end   = g_rowptr[v + 1];

    const float4* X4 = (const float4*)X + (size_t)b * NNODE * (CDIM / 4);
    float4 acc = make_float4(0.f, 0.f, 0.f, 0.f);

    for (int e0 = start; e0 < end; e0 += 64) {
        int ne = min(64, end - e0);
        if (t < ne) { ss[t] = g_csr_src[e0 + t]; sw[t] = g_csr_w[e0 + t]; }
        __syncthreads();
        #pragma unroll 4
        for (int i = 0; i < ne; i++) {
            float  w = sw[i];
            float4 x = X4[(size_t)ss[i] * (CDIM / 4) + t];
            acc.x += w * x.x; acc.y += w * x.y;
            acc.z += w * x.z; acc.w += w * x.w;
        }
        __syncthreads();
    }
    ((float4*)Y)[((size_t)b * NNODE + v) * (CDIM / 4) + t] = acc;
}

// ---------------- mma.sync helpers ----------------------------------------------------
__device__ __forceinline__ uint32_t smem_u32(const void* p) {
    uint32_t a;
    asm("{ .reg .u64 t; cvta.to.shared.u64 t, %1; cvt.u32.u64 %0, t; }" : "=r"(a) : "l"(p));
    return a;
}
__device__ __forceinline__ void ldsm_x4(uint32_t& r0, uint32_t& r1, uint32_t& r2, uint32_t& r3,
                                        uint32_t addr) {
    asm volatile("ldmatrix.sync.aligned.m8n8.x4.shared.b16 {%0,%1,%2,%3}, [%4];"
                 : "=r"(r0), "=r"(r1), "=r"(r2), "=r"(r3) : "r"(addr));
}
__device__ __forceinline__ void ldsm_x2t(uint32_t& r0, uint32_t& r1, uint32_t addr) {
    asm volatile("ldmatrix.sync.aligned.m8n8.x2.trans.shared.b16 {%0,%1}, [%2];"
                 : "=r"(r0), "=r"(r1) : "r"(addr));
}
__device__ __forceinline__ void mma_bf16(float* c, const uint32_t* a, uint32_t b0, uint32_t b1) {
    asm volatile("mma.sync.aligned.m16n8k16.row.col.f32.bf16.bf16.f32 "
                 "{%0,%1,%2,%3}, {%4,%5,%6,%7}, {%8,%9}, {%0,%1,%2,%3};"
                 : "+f"(c[0]), "+f"(c[1]), "+f"(c[2]), "+f"(c[3])
                 : "r"(a[0]), "r"(a[1]), "r"(a[2]), "r"(a[3]), "r"(b0), "r"(b1));
}
__device__ __forceinline__ void cp16(uint32_t dst, const void* src) {
    asm volatile("{ .reg .u64 g; cvta.to.global.u64 g, %1;\n\t"
                 "cp.async.ca.shared.global [%0], [g], 16; }" :: "r"(dst), "l"(src));
}

// ---------------- GEMM (mma.sync bf16 split) + bias + LayerNorm ----------------------
// out[160000,256] = [feats|Tx1|P2](M x 768) @ Wc + b, then row LN.
// CTA: M=64, N=256, BK=32. 8 warps = 2(M) x 4(N); warp tile 32 x 64.
// SMEM: A hi/lo [64][40] bf16 (single stage, reg-prefetched+converted),
//       B hi/lo [32][264] bf16 (double stage via cp.async).
#define A_LDS   40
#define A_ROWB  (A_LDS * 2)            // 80 bytes
#define A_HSZ   (64 * A_ROWB)          // 5120
#define A_SZ    (2 * A_HSZ)            // 10240
#define B_LDS   264
#define B_ROWB  (B_LDS * 2)            // 528 bytes
#define B_HSZ   (32 * B_ROWB)          // 16896
#define B_STG   (2 * B_HSZ)            // 33792
#define SMEM_DYN (A_SZ + 2 * B_STG)    // 77824

__global__ void __launch_bounds__(256, 2)
k_gemm_mma(const float* __restrict__ A0,
           const float* __restrict__ bias,
           const float* __restrict__ lnw,
           const float* __restrict__ lnb,
           float* __restrict__ out)
{
    extern __shared__ char smem[];
    const uint32_t sb = smem_u32(smem);
    const int tid  = threadIdx.x;
    const int wid  = tid >> 5;
    const int lane = tid & 31;
    const int wm   = wid >> 2;          // 0..1 (M)
    const int wn   = wid & 3;           // 0..3 (N)
    const int m0   = blockIdx.x * 64;

    float acc[2][8][4];
    #pragma unroll
    for (int mt = 0; mt < 2; mt++)
        #pragma unroll
        for (int nt = 0; nt < 8; nt++)
            #pragma unroll
            for (int q = 0; q < 4; q++) acc[mt][nt][q] = 0.0f;

    // A gmem coords: 2 float4 per thread covering [64][32] floats
    const int ar0 = tid >> 3;                 // row 0..31
    const int aq0 = tid & 7;
    const int ar1 = (tid + 256) >> 3;         // row 32..63
    const int aq1 = aq0;

    // --- prefetch chunk 0 ---
    const float* Aseg = A0;
    float4 pa0 = *(const float4*)(Aseg + (size_t)(m0 + ar0) * CDIM + aq0 * 4);
    float4 pa1 = *(const float4*)(Aseg + (size_t)(m0 + ar1) * CDIM + aq1 * 4);
    {
        uint32_t st = sb + A_SZ;              // stage 0
        #pragma unroll
        for (int h = 0; h < 2; h++) {
            const __nv_bfloat16* gw = h ? g_W_lo : g_W_hi;
            #pragma unroll
            for (int i = 0; i < 4; i++) {
                int idx = tid + 256 * i;      // 0..1023
                int row = idx >> 5;           // 0..31
                int q   = idx & 31;           // 16B chunk within 512B row
                cp16(st + h * B_HSZ + row * B_ROWB + q * 16,
                     gw + (size_t)row * 256 + q * 8);
            }
        }
        asm volatile("cp.async.commit_group;" ::: "memory");
    }

    for (int c = 0; c < 24; c++) {
        const int s = c & 1;
        const uint32_t sbB = sb + A_SZ + s * B_STG;

        asm volatile("cp.async.wait_group 0;" ::: "memory");
        __syncthreads();

        // ---- store prefetched A (convert fp32 -> bf16 hi/lo) ----
        {
            float4 x;
            int row, q;
            #pragma unroll
            for (int p = 0; p < 2; p++) {
                if (p == 0) { x = pa0; row = ar0; q = aq0; }
                else        { x = pa1; row = ar1; q = aq1; }
                __nv_bfloat16 h0 = __float2bfloat16(x.x), h1 = __float2bfloat16(x.y);
                __nv_bfloat16 h2 = __float2bfloat16(x.z), h3 = __float2bfloat16(x.w);
                __nv_bfloat16 l0 = __float2bfloat16(x.x - __bfloat162float(h0));
                __nv_bfloat16 l1 = __float2bfloat16(x.y - __bfloat162float(h1));
                __nv_bfloat16 l2 = __float2bfloat16(x.z - __bfloat162float(h2));
                __nv_bfloat16 l3 = __float2bfloat16(x.w - __bfloat162float(h3));
                uint32_t hp0 = ((uint32_t)__bfloat16_as_ushort(h1) << 16) | __bfloat16_as_ushort(h0);
                uint32_t hp1 = ((uint32_t)__bfloat16_as_ushort(h3) << 16) | __bfloat16_as_ushort(h2);
                uint32_t lp0 = ((uint32_t)__bfloat16_as_ushort(l1) << 16) | __bfloat16_as_ushort(l0);
                uint32_t lp1 = ((uint32_t)__bfloat16_as_ushort(l3) << 16) | __bfloat16_as_ushort(l2);
                *(uint2*)(smem + row * A_ROWB + q * 8)         = make_uint2(hp0, hp1);
                *(uint2*)(smem + A_HSZ + row * A_ROWB + q * 8) = make_uint2(lp0, lp1);
            }
        }
        __syncthreads();

        // ---- prefetch chunk c+1 ----
        if (c + 1 < 24) {
            int c1 = c + 1;
            int seg = c1 >> 3;
            Aseg = (seg == 0) ? A0 : (seg == 1) ? (const float*)g_Tx1 : (const float*)g_P2;
            int koff = (c1 & 7) * 32;
            pa0 = *(const float4*)(Aseg + (size_t)(m0 + ar0) * CDIM + koff + aq0 * 4);
            pa1 = *(const float4*)(Aseg + (size_t)(m0 + ar1) * CDIM + koff + aq1 * 4);

            uint32_t st = sb + A_SZ + ((c1 & 1) ? B_STG : 0);
            int kb = c1 * 32;
            #pragma unroll
            for (int h = 0; h < 2; h++) {
                const __nv_bfloat16* gw = h ? g_W_lo : g_W_hi;
                #pragma unroll
                for (int i = 0; i < 4; i++) {
                    int idx = tid + 256 * i;
                    int row = idx >> 5;
                    int q   = idx & 31;
                    cp16(st + h * B_HSZ + row * B_ROWB + q * 16,
                         gw + (size_t)(kb + row) * 256 + q * 8);
                }
            }
            asm volatile("cp.async.commit_group;" ::: "memory");
        }

        // ---- mma over BK=32 (2 k-steps of 16) ----
        #pragma unroll
        for (int k = 0; k < 2; k++) {
            uint32_t ah[2][4], al[2][4];
            #pragma unroll
            for (int mt = 0; mt < 2; mt++) {
                uint32_t arow = (uint32_t)(wm * 32 + mt * 16 + (lane & 15));
                uint32_t aoff = arow * A_ROWB + (uint32_t)(k * 32 + (lane >> 4) * 16);
                ldsm_x4(ah[mt][0], ah[mt][1], ah[mt][2], ah[mt][3], sb + aoff);
                ldsm_x4(al[mt][0], al[mt][1], al[mt][2], al[mt][3], sb + A_HSZ + aoff);
            }
            #pragma unroll
            for (int nt = 0; nt < 8; nt++) {
                uint32_t boff = (uint32_t)(k * 16 + (lane & 15)) * B_ROWB
                              + (uint32_t)(wn * 64 + nt * 8) * 2;
                uint32_t bh0, bh1, bl0, bl1;
                ldsm_x2t(bh0, bh1, sbB + boff);
                ldsm_x2t(bl0, bl1, sbB + B_HSZ + boff);
                #pragma unroll
                for (int mt = 0; mt < 2; mt++) {
                    mma_bf16(acc[mt][nt], ah[mt], bh0, bh1);
                    mma_bf16(acc[mt][nt], ah[mt], bl0, bl1);
                    mma_bf16(acc[mt][nt], al[mt], bh0, bh1);
                }
            }
        }
    }

    // ---- epilogue: acc -> SMEM, then LN per row ----
    __syncthreads();
    float* ep = (float*)(smem + A_SZ);        // [64][256], 64KB (aliases B stages)
    #pragma unroll
    for (int mt = 0; mt < 2; mt++) {
        int r0 = wm * 32 + mt * 16 + (lane >> 2);
        #pragma unroll
        for (int nt = 0; nt < 8; nt++) {
            int cbase = wn * 64 + nt * 8 + (lane & 3) * 2;
            *(float2*)(ep + r0 * 256 + cbase)       = make_float2(acc[mt][nt][0], acc[mt][nt][1]);
            *(float2*)(ep + (r0 + 8) * 256 + cbase) = make_float2(acc[mt][nt][2], acc[mt][nt][3]);
        }
    }
    __syncthreads();

    // warp wid handles rows wid*8..+8; lane covers cols {j*32+lane}
    float bb[8], lw[8], lb[8];
    #pragma unroll
    for (int j = 0; j < 8; j++) {
        int col = j * 32 + lane;
        bb[j] = bias[col]; lw[j] = lnw[col]; lb[j] = lnb[col];
    }
    #pragma unroll
    for (int i = 0; i < 8; i++) {
        int row = wid * 8 + i;
        float v[8];
        float s = 0.0f;
        #pragma unroll
        for (int j = 0; j < 8; j++) {
            v[j] = ep[row * 256 + j * 32 + lane] + bb[j];
            s += v[j];
        }
        #pragma unroll
        for (int o = 16; o > 0; o >>= 1) s += __shfl_xor_sync(0xffffffffu, s, o);
        float mu = s * (1.0f / CDIM);
        float s2 = 0.0f;
        #pragma unroll
        for (int j = 0; j < 8; j++) { float d = v[j] - mu; s2 += d * d; }
        #pragma unroll
        for (int o = 16; o > 0; o >>= 1) s2 += __shfl_xor_sync(0xffffffffu, s2, o);
        float inv = rsqrtf(s2 * (1.0f / CDIM) + 1e-5f);

        size_t rbase = ((size_t)m0 + row) * CDIM;
        #pragma unroll
        for (int j = 0; j < 8; j++)
            out[rbase + j * 32 + lane] = (v[j] - mu) * inv * lw[j] + lb[j];
    }
}

// ---------------- launch -------------------------------------------------------------
extern "C" void kernel_launch(void* const* d_in, const int* in_sizes, int n_in,
                              void* d_out, int out_size) {
    const float* feats = (const float*)d_in[0];      // [B*N, C]
    const float* W     = (const float*)d_in[1];      // [L,K,C,C]
    const float* bpar  = (const float*)d_in[2];      // [L,C]
    const float* lnw   = (const float*)d_in[3];      // [L,C]
    const float* lnb   = (const float*)d_in[4];      // [L,C]
    const int*   ei    = (const int*)d_in[5];        // [2,E] int32 OR int64 (detected)
    float* out = (float*)d_out;

    cudaFuncSetAttribute(k_gemm_mma, cudaFuncAttributeMaxDynamicSharedMemorySize, SMEM_DYN);

    k_zero  <<<(NNODE + 255) / 256, 256>>>();
    k_detect<<<1, 256>>>(ei);
    k_deg   <<<(NEDGE + 255) / 256, 256>>>(ei);
    k_dis   <<<(NNODE + 255) / 256, 256>>>();
    k_scan  <<<1, 1024>>>();
    k_fill  <<<(NEDGE + 255) / 256, 256>>>(ei);
    k_wc    <<<(3 * CDIM * CDIM) / 256, 256>>>(W);

    k_prop<<<dim3(NNODE, BATCH), 64>>>(feats, 0);   // Tx1 = A_hat @ feats
    k_prop<<<dim3(NNODE, BATCH), 64>>>(nullptr, 1); // P2  = A_hat @ Tx1

    // only layer 1 survives in the reference -> use its params
    k_gemm_mma<<<(BATCH * NNODE) / 64, 256, SMEM_DYN>>>(
        feats, bpar + CDIM, lnw + CDIM, lnb + CDIM, out);
}

// round 10
// speedup vs baseline: 2.7295x; 1.0281x over previous
#include <cuda_runtime.h>
#include <cuda_bf16.h>
#include <cuda_fp16.h>
#include <cstdint>

// Problem constants (fixed by the reference)
#define BATCH  8
#define NNODE  20000
#define CDIM   256
#define NEDGE  320000

// ---------------- device scratch (allocation-free rule: __device__ globals) ---------
__device__ int   g_hi_nonzero;          // 1 => edge_index buffer is int32
__device__ int   g_deg[NNODE];
__device__ int   g_cnt[NNODE];
__device__ int   g_cursor[NNODE];
__device__ float g_dis[NNODE];
__device__ int   g_rowptr[NNODE + 1];
__device__ int   g_csr_src[NEDGE];
__device__ float g_csr_w[NEDGE];
__device__ float g_Tx1[(size_t)BATCH * NNODE * CDIM];   // 163.8 MB (fp32, GEMM A seg1)
__device__ float g_P2 [(size_t)BATCH * NNODE * CDIM];   // 163.8 MB (fp32, GEMM A seg2)
__device__ __half g_feats16[(size_t)BATCH * NNODE * CDIM]; // 81.9 MB (gather plane)
__device__ __half g_Tx116  [(size_t)BATCH * NNODE * CDIM]; // 81.9 MB (gather plane)
// folded layer-1 weights, bf16 split precision, [K=768][N=256] row-major
__device__ __nv_bfloat16 g_W_hi[768 * 256];
__device__ __nv_bfloat16 g_W_lo[768 * 256];

// ---------------- dtype detection ---------------------------------------------------
// Node indices < 20000 -> int64 storage has zero high words everywhere.
__global__ void k_detect(const int* __restrict__ p32) {
    int t = threadIdx.x;
    if (p32[2 * t + 1] != 0) atomicOr(&g_hi_nonzero, 1);
}
__device__ __forceinline__ void load_edge(const int* __restrict__ p, int e, int& s, int& d) {
    if (g_hi_nonzero) { s = p[e];      d = p[NEDGE + e]; }
    else              { s = p[2 * e];  d = p[2 * (NEDGE + e)]; }
}

// ---------------- graph prep kernels ------------------------------------------------
__global__ void k_zero() {
    int i = blockIdx.x * blockDim.x + threadIdx.x;
    if (i < NNODE) { g_deg[i] = 0; g_cnt[i] = 0; g_cursor[i] = 0; }
    if (i == 0) g_hi_nonzero = 0;
}
__global__ void k_deg(const int* __restrict__ ei) {
    int e = blockIdx.x * blockDim.x + threadIdx.x;
    if (e < NEDGE) {
        int s, d; load_edge(ei, e, s, d);
        atomicAdd(&g_deg[s], 1);
        atomicAdd(&g_cnt[d], 1);
    }
}
__global__ void k_dis() {
    int i = blockIdx.x * blockDim.x + threadIdx.x;
    if (i < NNODE) {
        int d = g_deg[i];
        g_dis[i] = (d > 0) ? rsqrtf((float)d) : 0.0f;
    }
}
__global__ void k_scan() {
    __shared__ int sh[1024];
    const int CH = 20;
    int t = threadIdx.x;
    int base = t * CH;
    int sum = 0;
    for (int i = 0; i < CH; i++) { int idx = base + i; if (idx < NNODE) sum += g_cnt[idx]; }
    sh[t] = sum;
    __syncthreads();
    for (int o = 1; o < 1024; o <<= 1) {
        int v = (t >= o) ? sh[t - o] : 0;
        __syncthreads();
        sh[t] += v;
        __syncthreads();
    }
    int run = sh[t] - sum;
    for (int i = 0; i < CH; i++) {
        int idx = base + i;
        if (idx < NNODE) { g_rowptr[idx] = run; run += g_cnt[idx]; }
    }
    if (t == 1023) g_rowptr[NNODE] = sh[1023];
}
__global__ void k_fill(const int* __restrict__ ei) {
    int e = blockIdx.x * blockDim.x + threadIdx.x;
    if (e < NEDGE) {
        int s, d; load_edge(ei, e, s, d);
        float w = -g_dis[s] * g_dis[d];
        int pos = atomicAdd(&g_cursor[d], 1);
        int idx = g_rowptr[d] + pos;
        g_csr_src[idx] = s;
        g_csr_w[idx]   = w;
    }
}

// convert feats fp32 -> fp16 gather plane
__global__ void k_half(const float* __restrict__ f) {
    size_t i = (size_t)blockIdx.x * blockDim.x + threadIdx.x;   // over elems/4
    float4 x = ((const float4*)f)[i];
    __half2 a = __floats2half2_rn(x.x, x.y);
    __half2 b = __floats2half2_rn(x.z, x.w);
    uint2 p;
    p.x = *(uint32_t*)&a;
    p.y = *(uint32_t*)&b;
    ((uint2*)g_feats16)[i] = p;
}

// fold layer-1 weights into bf16 hi/lo, [K=768][N=256]:
// Wc = [W0-W2 ; W1 ; 2*W2]  (since Tx2 = 2*P2 - Tx0)
__global__ void k_wc(const float* __restrict__ W) {
    int idx = blockIdx.x * blockDim.x + threadIdx.x;   // < 3*256*256, = kg*256 + n
    const int CC = CDIM * CDIM;
    int seg = idx / CC;
    int r   = idx - seg * CC;
    const float* Wl = W + 1 * 3 * CC;  // layer 1
    float v;
    if      (seg == 0) v = Wl[r] - Wl[2 * CC + r];
    else if (seg == 1) v = Wl[CC + r];
    else               v = 2.0f * Wl[2 * CC + r];
    __nv_bfloat16 h = __float2bfloat16(v);
    float lo = v - __bfloat162float(h);
    g_W_hi[idx] = h;
    g_W_lo[idx] = __float2bfloat16(lo);
}

// ---------------- propagation: Y[b,v,:] = sum_e norm[e] * X[b,src[e],:] ------------
// fp16 gather planes, fp32 accumulate. phase 0: X=g_feats16 -> g_Tx1 (fp32) + g_Tx116
// (fp16). phase 1: X=g_Tx116 -> g_P2 (fp32).
__global__ void k_prop(int phase) {
    const __half* X16 = (phase == 0) ? g_feats16 : g_Tx116;
    float*        Yf  = (phase == 0) ? g_Tx1 : g_P2;

    int v = blockIdx.x;
    int b = blockIdx.y;
    int t = threadIdx.x;                   // 0..63, each owns 4 channels

    __shared__ int   ss[64];
    __shared__ float sw[64];

    int start = g_rowptr[v];
    int end   = g_rowptr[v + 1];

    const uint2* X8 = (const uint2*)X16 + (size_t)b * NNODE * (CDIM / 4);
    float4 acc = make_float4(0.f, 0.f, 0.f, 0.f);

    for (int e0 = start; e0 < end; e0 += 64) {
        int ne = min(64, end - e0);
        if (t < ne) { ss[t] = g_csr_src[e0 + t]; sw[t] = g_csr_w[e0 + t]; }
        __syncthreads();
        #pragma unroll 4
        for (int i = 0; i < ne; i++) {
            float w = sw[i];
            uint2 raw = X8[(size_t)ss[i] * (CDIM / 4) + t];
            __half2 h0 = *(__half2*)&raw.x;
            __half2 h1 = *(__half2*)&raw.y;
            float2 f0 = __half22float2(h0);
            float2 f1 = __half22float2(h1);
            acc.x += w * f0.x; acc.y += w * f0.y;
            acc.z += w * f1.x; acc.w += w * f1.y;
        }
        __syncthreads();
    }
    size_t o = ((size_t)b * NNODE + v) * (CDIM / 4) + t;
    ((float4*)Yf)[o] = acc;
    if (phase == 0) {
        __half2 o0 = __floats2half2_rn(acc.x, acc.y);
        __half2 o1 = __floats2half2_rn(acc.z, acc.w);
        uint2 p;
        p.x = *(uint32_t*)&o0;
        p.y = *(uint32_t*)&o1;
        ((uint2*)g_Tx116)[o] = p;
    }
}

// ---------------- mma.sync helpers ----------------------------------------------------
__device__ __forceinline__ uint32_t smem_u32(const void* p) {
    uint32_t a;
    asm("{ .reg .u64 t; cvta.to.shared.u64 t, %1; cvt.u32.u64 %0, t; }" : "=r"(a) : "l"(p));
    return a;
}
__device__ __forceinline__ void ldsm_x4(uint32_t& r0, uint32_t& r1, uint32_t& r2, uint32_t& r3,
                                        uint32_t addr) {
    asm volatile("ldmatrix.sync.aligned.m8n8.x4.shared.b16 {%0,%1,%2,%3}, [%4];"
                 : "=r"(r0), "=r"(r1), "=r"(r2), "=r"(r3) : "r"(addr));
}
__device__ __forceinline__ void ldsm_x2t(uint32_t& r0, uint32_t& r1, uint32_t addr) {
    asm volatile("ldmatrix.sync.aligned.m8n8.x2.trans.shared.b16 {%0,%1}, [%2];"
                 : "=r"(r0), "=r"(r1) : "r"(addr));
}
__device__ __forceinline__ void mma_bf16(float* c, const uint32_t* a, uint32_t b0, uint32_t b1) {
    asm volatile("mma.sync.aligned.m16n8k16.row.col.f32.bf16.bf16.f32 "
                 "{%0,%1,%2,%3}, {%4,%5,%6,%7}, {%8,%9}, {%0,%1,%2,%3};"
                 : "+f"(c[0]), "+f"(c[1]), "+f"(c[2]), "+f"(c[3])
                 : "r"(a[0]), "r"(a[1]), "r"(a[2]), "r"(a[3]), "r"(b0), "r"(b1));
}
__device__ __forceinline__ void cp16(uint32_t dst, const void* src) {
    asm volatile("{ .reg .u64 g; cvta.to.global.u64 g, %1;\n\t"
                 "cp.async.ca.shared.global [%0], [g], 16; }" :: "r"(dst), "l"(src));
}

// ---------------- GEMM (mma.sync bf16 split) + bias + LayerNorm ----------------------
// out[160000,256] = [feats|Tx1|P2](M x 768) @ Wc + b, then row LN.
// CTA: M=64, N=256, BK=32. 8 warps = 2(M) x 4(N); warp tile 32 x 64.
// SMEM: A hi/lo [64][40] bf16 (single stage, reg-prefetched+converted),
//       B hi/lo [32][264] bf16 (double stage via cp.async).
#define A_LDS   40
#define A_ROWB  (A_LDS * 2)            // 80 bytes
#define A_HSZ   (64 * A_ROWB)          // 5120
#define A_SZ    (2 * A_HSZ)            // 10240
#define B_LDS   264
#define B_ROWB  (B_LDS * 2)            // 528 bytes
#define B_HSZ   (32 * B_ROWB)          // 16896
#define B_STG   (2 * B_HSZ)            // 33792
#define SMEM_DYN (A_SZ + 2 * B_STG)    // 77824

__global__ void __launch_bounds__(256, 2)
k_gemm_mma(const float* __restrict__ A0,
           const float* __restrict__ bias,
           const float* __restrict__ lnw,
           const float* __restrict__ lnb,
           float* __restrict__ out)
{
    extern __shared__ char smem[];
    const uint32_t sb = smem_u32(smem);
    const int tid  = threadIdx.x;
    const int wid  = tid >> 5;
    const int lane = tid & 31;
    const int wm   = wid >> 2;          // 0..1 (M)
    const int wn   = wid & 3;           // 0..3 (N)
    const int m0   = blockIdx.x * 64;

    float acc[2][8][4];
    #pragma unroll
    for (int mt = 0; mt < 2; mt++)
        #pragma unroll
        for (int nt = 0; nt < 8; nt++)
            #pragma unroll
            for (int q = 0; q < 4; q++) acc[mt][nt][q] = 0.0f;

    // A gmem coords: 2 float4 per thread covering [64][32] floats
    const int ar0 = tid >> 3;                 // row 0..31
    const int aq0 = tid & 7;
    const int ar1 = (tid + 256) >> 3;         // row 32..63
    const int aq1 = aq0;

    // --- prefetch chunk 0 ---
    const float* Aseg = A0;
    float4 pa0 = *(const float4*)(Aseg + (size_t)(m0 + ar0) * CDIM + aq0 * 4);
    float4 pa1 = *(const float4*)(Aseg + (size_t)(m0 + ar1) * CDIM + aq1 * 4);
    {
        uint32_t st = sb + A_SZ;              // stage 0
        #pragma unroll
        for (int h = 0; h < 2; h++) {
            const __nv_bfloat16* gw = h ? g_W_lo : g_W_hi;
            #pragma unroll
            for (int i = 0; i < 4; i++) {
                int idx = tid + 256 * i;      // 0..1023
                int row = idx >> 5;           // 0..31
                int q   = idx & 31;           // 16B chunk within 512B row
                cp16(st + h * B_HSZ + row * B_ROWB + q * 16,
                     gw + (size_t)row * 256 + q * 8);
            }
        }
        asm volatile("cp.async.commit_group;" ::: "memory");
    }

    for (int c = 0; c < 24; c++) {
        const int s = c & 1;
        const uint32_t sbB = sb + A_SZ + s * B_STG;

        asm volatile("cp.async.wait_group 0;" ::: "memory");
        __syncthreads();

        // ---- store prefetched A (convert fp32 -> bf16 hi/lo) ----
        {
            float4 x;
            int row, q;
            #pragma unroll
            for (int p = 0; p < 2; p++) {
                if (p == 0) { x = pa0; row = ar0; q = aq0; }
                else        { x = pa1; row = ar1; q = aq1; }
                __nv_bfloat16 h0 = __float2bfloat16(x.x), h1 = __float2bfloat16(x.y);
                __nv_bfloat16 h2 = __float2bfloat16(x.z), h3 = __float2bfloat16(x.w);
                __nv_bfloat16 l0 = __float2bfloat16(x.x - __bfloat162float(h0));
                __nv_bfloat16 l1 = __float2bfloat16(x.y - __bfloat162float(h1));
                __nv_bfloat16 l2 = __float2bfloat16(x.z - __bfloat162float(h2));
                __nv_bfloat16 l3 = __float2bfloat16(x.w - __bfloat162float(h3));
                uint32_t hp0 = ((uint32_t)__bfloat16_as_ushort(h1) << 16) | __bfloat16_as_ushort(h0);
                uint32_t hp1 = ((uint32_t)__bfloat16_as_ushort(h3) << 16) | __bfloat16_as_ushort(h2);
                uint32_t lp0 = ((uint32_t)__bfloat16_as_ushort(l1) << 16) | __bfloat16_as_ushort(l0);
                uint32_t lp1 = ((uint32_t)__bfloat16_as_ushort(l3) << 16) | __bfloat16_as_ushort(l2);
                *(uint2*)(smem + row * A_ROWB + q * 8)         = make_uint2(hp0, hp1);
                *(uint2*)(smem + A_HSZ + row * A_ROWB + q * 8) = make_uint2(lp0, lp1);
            }
        }
        __syncthreads();

        // ---- prefetch chunk c+1 ----
        if (c + 1 < 24) {
            int c1 = c + 1;
            int seg = c1 >> 3;
            Aseg = (seg == 0) ? A0 : (seg == 1) ? (const float*)g_Tx1 : (const float*)g_P2;
            int koff = (c1 & 7) * 32;
            pa0 = *(const float4*)(Aseg + (size_t)(m0 + ar0) * CDIM + koff + aq0 * 4);
            pa1 = *(const float4*)(Aseg + (size_t)(m0 + ar1) * CDIM + koff + aq1 * 4);

            uint32_t st = sb + A_SZ + ((c1 & 1) ? B_STG : 0);
            int kb = c1 * 32;
            #pragma unroll
            for (int h = 0; h < 2; h++) {
                const __nv_bfloat16* gw = h ? g_W_lo : g_W_hi;
                #pragma unroll
                for (int i = 0; i < 4; i++) {
                    int idx = tid + 256 * i;
                    int row = idx >> 5;
                    int q   = idx & 31;
                    cp16(st + h * B_HSZ + row * B_ROWB + q * 16,
                         gw + (size_t)(kb + row) * 256 + q * 8);
                }
            }
            asm volatile("cp.async.commit_group;" ::: "memory");
        }

        // ---- mma over BK=32 (2 k-steps of 16) ----
        #pragma unroll
        for (int k = 0; k < 2; k++) {
            uint32_t ah[2][4], al[2][4];
            #pragma unroll
            for (int mt = 0; mt < 2; mt++) {
                uint32_t arow = (uint32_t)(wm * 32 + mt * 16 + (lane & 15));
                uint32_t aoff = arow * A_ROWB + (uint32_t)(k * 32 + (lane >> 4) * 16);
                ldsm_x4(ah[mt][0], ah[mt][1], ah[mt][2], ah[mt][3], sb + aoff);
                ldsm_x4(al[mt][0], al[mt][1], al[mt][2], al[mt][3], sb + A_HSZ + aoff);
            }
            #pragma unroll
            for (int nt = 0; nt < 8; nt++) {
                uint32_t boff = (uint32_t)(k * 16 + (lane & 15)) * B_ROWB
                              + (uint32_t)(wn * 64 + nt * 8) * 2;
                uint32_t bh0, bh1, bl0, bl1;
                ldsm_x2t(bh0, bh1, sbB + boff);
                ldsm_x2t(bl0, bl1, sbB + B_HSZ + boff);
                #pragma unroll
                for (int mt = 0; mt < 2; mt++) {
                    mma_bf16(acc[mt][nt], ah[mt], bh0, bh1);
                    mma_bf16(acc[mt][nt], ah[mt], bl0, bl1);
                    mma_bf16(acc[mt][nt], al[mt], bh0, bh1);
                }
            }
        }
    }

    // ---- epilogue: acc -> SMEM, then LN per row ----
    __syncthreads();
    float* ep = (float*)(smem + A_SZ);        // [64][256], 64KB (aliases B stages)
    #pragma unroll
    for (int mt = 0; mt < 2; mt++) {
        int r0 = wm * 32 + mt * 16 + (lane >> 2);
        #pragma unroll
        for (int nt = 0; nt < 8; nt++) {
            int cbase = wn * 64 + nt * 8 + (lane & 3) * 2;
            *(float2*)(ep + r0 * 256 + cbase)       = make_float2(acc[mt][nt][0], acc[mt][nt][1]);
            *(float2*)(ep + (r0 + 8) * 256 + cbase) = make_float2(acc[mt][nt][2], acc[mt][nt][3]);
        }
    }
    __syncthreads();

    // warp wid handles rows wid*8..+8; lane covers cols {j*32+lane}
    float bb[8], lw[8], lb[8];
    #pragma unroll
    for (int j = 0; j < 8; j++) {
        int col = j * 32 + lane;
        bb[j] = bias[col]; lw[j] = lnw[col]; lb[j] = lnb[col];
    }
    #pragma unroll
    for (int i = 0; i < 8; i++) {
        int row = wid * 8 + i;
        float v[8];
        float s = 0.0f;
        #pragma unroll
        for (int j = 0; j < 8; j++) {
            v[j] = ep[row * 256 + j * 32 + lane] + bb[j];
            s += v[j];
        }
        #pragma unroll
        for (int o = 16; o > 0; o >>= 1) s += __shfl_xor_sync(0xffffffffu, s, o);
        float mu = s * (1.0f / CDIM);
        float s2 = 0.0f;
        #pragma unroll
        for (int j = 0; j < 8; j++) { float d = v[j] - mu; s2 += d * d; }
        #pragma unroll
        for (int o = 16; o > 0; o >>= 1) s2 += __shfl_xor_sync(0xffffffffu, s2, o);
        float inv = rsqrtf(s2 * (1.0f / CDIM) + 1e-5f);

        size_t rbase = ((size_t)m0 + row) * CDIM;
        #pragma unroll
        for (int j = 0; j < 8; j++)
            out[rbase + j * 32 + lane] = (v[j] - mu) * inv * lw[j] + lb[j];
    }
}

// ---------------- launch -------------------------------------------------------------
extern "C" void kernel_launch(void* const* d_in, const int* in_sizes, int n_in,
                              void* d_out, int out_size) {
    const float* feats = (const float*)d_in[0];      // [B*N, C]
    const float* W     = (const float*)d_in[1];      // [L,K,C,C]
    const float* bpar  = (const float*)d_in[2];      // [L,C]
    const float* lnw   = (const float*)d_in[3];      // [L,C]
    const float* lnb   = (const float*)d_in[4];      // [L,C]
    const int*   ei    = (const int*)d_in[5];        // [2,E] int32 OR int64 (detected)
    float* out = (float*)d_out;

    cudaFuncSetAttribute(k_gemm_mma, cudaFuncAttributeMaxDynamicSharedMemorySize, SMEM_DYN);

    k_zero  <<<(NNODE + 255) / 256, 256>>>();
    k_detect<<<1, 256>>>(ei);
    k_deg   <<<(NEDGE + 255) / 256, 256>>>(ei);
    k_dis   <<<(NNODE + 255) / 256, 256>>>();
    k_scan  <<<1, 1024>>>();
    k_fill  <<<(NEDGE + 255) / 256, 256>>>(ei);
    k_wc    <<<(3 * CDIM * CDIM) / 256, 256>>>(W);
    k_half  <<<(BATCH * NNODE * CDIM / 4) / 256, 256>>>(feats);

    k_prop<<<dim3(NNODE, BATCH), 64>>>(0);   // Tx1 = A_hat @ feats   (fp16 gather)
    k_prop<<<dim3(NNODE, BATCH), 64>>>(1);   // P2  = A_hat @ Tx1     (fp16 gather)

    // only layer 1 survives in the reference -> use its params
    k_gemm_mma<<<(BATCH * NNODE) / 64, 256, SMEM_DYN>>>(
        feats, bpar + CDIM, lnw + CDIM, lnb + CDIM, out);
}

// round 11
// speedup vs baseline: 2.7624x; 1.0121x over previous
#include <cuda_runtime.h>
#include <cuda_bf16.h>
#include <cuda_fp16.h>
#include <cstdint>

// Problem constants (fixed by the reference)
#define BATCH  8
#define NNODE  20000
#define CDIM   256
#define NEDGE  320000

// ---------------- device scratch (allocation-free rule: __device__ globals) ---------
__device__ int   g_hi_nonzero;          // 1 => edge_index buffer is int32
__device__ int   g_deg[NNODE];
__device__ int   g_cnt[NNODE];
__device__ int   g_cursor[NNODE];
__device__ float g_dis[NNODE];
__device__ int   g_rowptr[NNODE + 1];
__device__ int   g_csr_src[NEDGE];
__device__ float g_csr_w[NEDGE];
__device__ float g_Tx1[(size_t)BATCH * NNODE * CDIM];   // 163.8 MB (fp32, GEMM A seg1)
__device__ float g_P2 [(size_t)BATCH * NNODE * CDIM];   // 163.8 MB (fp32, GEMM A seg2)
__device__ __half g_feats16[(size_t)BATCH * NNODE * CDIM]; // 81.9 MB (gather plane)
__device__ __half g_Tx116  [(size_t)BATCH * NNODE * CDIM]; // 81.9 MB (gather plane)
// folded layer-1 weights, bf16 split precision, [K=768][N=256] row-major
__device__ __nv_bfloat16 g_W_hi[768 * 256];
__device__ __nv_bfloat16 g_W_lo[768 * 256];

// ---------------- dtype detection ---------------------------------------------------
// Node indices < 20000 -> int64 storage has zero high words everywhere.
__global__ void k_detect(const int* __restrict__ p32) {
    int t = threadIdx.x;
    if (p32[2 * t + 1] != 0) atomicOr(&g_hi_nonzero, 1);
}
__device__ __forceinline__ void load_edge(const int* __restrict__ p, int e, int& s, int& d) {
    if (g_hi_nonzero) { s = p[e];      d = p[NEDGE + e]; }
    else              { s = p[2 * e];  d = p[2 * (NEDGE + e)]; }
}

// ---------------- graph prep kernels ------------------------------------------------
__global__ void k_zero() {
    int i = blockIdx.x * blockDim.x + threadIdx.x;
    if (i < NNODE) { g_deg[i] = 0; g_cnt[i] = 0; g_cursor[i] = 0; }
    if (i == 0) g_hi_nonzero = 0;
}
__global__ void k_deg(const int* __restrict__ ei) {
    int e = blockIdx.x * blockDim.x + threadIdx.x;
    if (e < NEDGE) {
        int s, d; load_edge(ei, e, s, d);
        atomicAdd(&g_deg[s], 1);
        atomicAdd(&g_cnt[d], 1);
    }
}
__global__ void k_dis() {
    int i = blockIdx.x * blockDim.x + threadIdx.x;
    if (i < NNODE) {
        int d = g_deg[i];
        g_dis[i] = (d > 0) ? rsqrtf((float)d) : 0.0f;
    }
}
__global__ void k_scan() {
    __shared__ int sh[1024];
    const int CH = 20;
    int t = threadIdx.x;
    int base = t * CH;
    int sum = 0;
    for (int i = 0; i < CH; i++) { int idx = base + i; if (idx < NNODE) sum += g_cnt[idx]; }
    sh[t] = sum;
    __syncthreads();
    for (int o = 1; o < 1024; o <<= 1) {
        int v = (t >= o) ? sh[t - o] : 0;
        __syncthreads();
        sh[t] += v;
        __syncthreads();
    }
    int run = sh[t] - sum;
    for (int i = 0; i < CH; i++) {
        int idx = base + i;
        if (idx < NNODE) { g_rowptr[idx] = run; run += g_cnt[idx]; }
    }
    if (t == 1023) g_rowptr[NNODE] = sh[1023];
}
__global__ void k_fill(const int* __restrict__ ei) {
    int e = blockIdx.x * blockDim.x + threadIdx.x;
    if (e < NEDGE) {
        int s, d; load_edge(ei, e, s, d);
        float w = -g_dis[s] * g_dis[d];
        int pos = atomicAdd(&g_cursor[d], 1);
        int idx = g_rowptr[d] + pos;
        g_csr_src[idx] = s;
        g_csr_w[idx]   = w;
    }
}

// convert feats fp32 -> fp16 gather plane
__global__ void k_half(const float* __restrict__ f) {
    size_t i = (size_t)blockIdx.x * blockDim.x + threadIdx.x;   // over elems/4
    float4 x = ((const float4*)f)[i];
    __half2 a = __floats2half2_rn(x.x, x.y);
    __half2 b = __floats2half2_rn(x.z, x.w);
    uint2 p;
    p.x = *(uint32_t*)&a;
    p.y = *(uint32_t*)&b;
    ((uint2*)g_feats16)[i] = p;
}

// fold layer-1 weights into bf16 hi/lo, [K=768][N=256]:
// Wc = [W0-W2 ; W1 ; 2*W2]  (since Tx2 = 2*P2 - Tx0)
__global__ void k_wc(const float* __restrict__ W) {
    int idx = blockIdx.x * blockDim.x + threadIdx.x;   // < 3*256*256, = kg*256 + n
    const int CC = CDIM * CDIM;
    int seg = idx / CC;
    int r   = idx - seg * CC;
    const float* Wl = W + 1 * 3 * CC;  // layer 1
    float v;
    if      (seg == 0) v = Wl[r] - Wl[2 * CC + r];
    else if (seg == 1) v = Wl[CC + r];
    else               v = 2.0f * Wl[2 * CC + r];
    __nv_bfloat16 h = __float2bfloat16(v);
    float lo = v - __bfloat162float(h);
    g_W_hi[idx] = h;
    g_W_lo[idx] = __float2bfloat16(lo);
}

// ---------------- propagation: Y[b,v,:] = sum_e norm[e] * X[b,src[e],:] ------------
// Warp-per-node, barrier-free. Lane owns 8 fp16 channels (one uint4 = 16B of the
// 512B row). Edge indices read per-iteration (warp-uniform -> L1 broadcast).
// phase 0: X=g_feats16 -> g_Tx1 (fp32) + g_Tx116 (fp16). phase 1: X=g_Tx116 -> g_P2.
__global__ void __launch_bounds__(256, 8)
k_prop(int phase) {
    const __half* X16 = (phase == 0) ? g_feats16 : g_Tx116;
    float*        Yf  = (phase == 0) ? g_Tx1 : g_P2;

    int wid  = threadIdx.x >> 5;           // warp in CTA (0..7)
    int lane = threadIdx.x & 31;
    int v    = blockIdx.x * 8 + wid;       // node
    int b    = blockIdx.y;                 // batch

    int start = g_rowptr[v];
    int end   = g_rowptr[v + 1];

    const uint4* X = (const uint4*)(X16 + (size_t)b * NNODE * CDIM);   // 32 uint4/row

    float acc[8];
    #pragma unroll
    for (int j = 0; j < 8; j++) acc[j] = 0.0f;

    #pragma unroll 4
    for (int e = start; e < end; e++) {
        int   s = __ldg(&g_csr_src[e]);     // warp-uniform broadcast
        float w = __ldg(&g_csr_w[e]);
        uint4 raw = X[(size_t)s * 32 + lane];
        float2 f0 = __half22float2(*(__half2*)&raw.x);
        float2 f1 = __half22float2(*(__half2*)&raw.y);
        float2 f2 = __half22float2(*(__half2*)&raw.z);
        float2 f3 = __half22float2(*(__half2*)&raw.w);
        acc[0] += w * f0.x; acc[1] += w * f0.y;
        acc[2] += w * f1.x; acc[3] += w * f1.y;
        acc[4] += w * f2.x; acc[5] += w * f2.y;
        acc[6] += w * f3.x; acc[7] += w * f3.y;
    }

    size_t rowf = ((size_t)b * NNODE + v) * CDIM + lane * 8;
    *(float4*)(Yf + rowf)     = make_float4(acc[0], acc[1], acc[2], acc[3]);
    *(float4*)(Yf + rowf + 4) = make_float4(acc[4], acc[5], acc[6], acc[7]);

    if (phase == 0) {
        __half2 o0 = __floats2half2_rn(acc[0], acc[1]);
        __half2 o1 = __floats2half2_rn(acc[2], acc[3]);
        __half2 o2 = __floats2half2_rn(acc[4], acc[5]);
        __half2 o3 = __floats2half2_rn(acc[6], acc[7]);
        uint4 p;
        p.x = *(uint32_t*)&o0; p.y = *(uint32_t*)&o1;
        p.z = *(uint32_t*)&o2; p.w = *(uint32_t*)&o3;
        ((uint4*)(g_Tx116 + (size_t)b * NNODE * CDIM))[(size_t)v * 32 + lane] = p;
    }
}

// ---------------- mma.sync helpers ----------------------------------------------------
__device__ __forceinline__ uint32_t smem_u32(const void* p) {
    uint32_t a;
    asm("{ .reg .u64 t; cvta.to.shared.u64 t, %1; cvt.u32.u64 %0, t; }" : "=r"(a) : "l"(p));
    return a;
}
__device__ __forceinline__ void ldsm_x4(uint32_t& r0, uint32_t& r1, uint32_t& r2, uint32_t& r3,
                                        uint32_t addr) {
    asm volatile("ldmatrix.sync.aligned.m8n8.x4.shared.b16 {%0,%1,%2,%3}, [%4];"
                 : "=r"(r0), "=r"(r1), "=r"(r2), "=r"(r3) : "r"(addr));
}
__device__ __forceinline__ void ldsm_x2t(uint32_t& r0, uint32_t& r1, uint32_t addr) {
    asm volatile("ldmatrix.sync.aligned.m8n8.x2.trans.shared.b16 {%0,%1}, [%2];"
                 : "=r"(r0), "=r"(r1) : "r"(addr));
}
__device__ __forceinline__ void mma_bf16(float* c, const uint32_t* a, uint32_t b0, uint32_t b1) {
    asm volatile("mma.sync.aligned.m16n8k16.row.col.f32.bf16.bf16.f32 "
                 "{%0,%1,%2,%3}, {%4,%5,%6,%7}, {%8,%9}, {%0,%1,%2,%3};"
                 : "+f"(c[0]), "+f"(c[1]), "+f"(c[2]), "+f"(c[3])
                 : "r"(a[0]), "r"(a[1]), "r"(a[2]), "r"(a[3]), "r"(b0), "r"(b1));
}
__device__ __forceinline__ void cp16(uint32_t dst, const void* src) {
    asm volatile("{ .reg .u64 g; cvta.to.global.u64 g, %1;\n\t"
                 "cp.async.ca.shared.global [%0], [g], 16; }" :: "r"(dst), "l"(src));
}

// ---------------- GEMM (mma.sync bf16 split) + bias + LayerNorm ----------------------
// out[160000,256] = [feats|Tx1|P2](M x 768) @ Wc + b, then row LN.
// CTA: M=64, N=256, BK=32. 8 warps = 2(M) x 4(N); warp tile 32 x 64.
// SMEM: A hi/lo [64][40] bf16 (single stage, reg-prefetched+converted),
//       B hi/lo [32][264] bf16 (double stage via cp.async).
#define A_LDS   40
#define A_ROWB  (A_LDS * 2)            // 80 bytes
#define A_HSZ   (64 * A_ROWB)          // 5120
#define A_SZ    (2 * A_HSZ)            // 10240
#define B_LDS   264
#define B_ROWB  (B_LDS * 2)            // 528 bytes
#define B_HSZ   (32 * B_ROWB)          // 16896
#define B_STG   (2 * B_HSZ)            // 33792
#define SMEM_DYN (A_SZ + 2 * B_STG)    // 77824

__global__ void __launch_bounds__(256, 2)
k_gemm_mma(const float* __restrict__ A0,
           const float* __restrict__ bias,
           const float* __restrict__ lnw,
           const float* __restrict__ lnb,
           float* __restrict__ out)
{
    extern __shared__ char smem[];
    const uint32_t sb = smem_u32(smem);
    const int tid  = threadIdx.x;
    const int wid  = tid >> 5;
    const int lane = tid & 31;
    const int wm   = wid >> 2;          // 0..1 (M)
    const int wn   = wid & 3;           // 0..3 (N)
    const int m0   = blockIdx.x * 64;

    float acc[2][8][4];
    #pragma unroll
    for (int mt = 0; mt < 2; mt++)
        #pragma unroll
        for (int nt = 0; nt < 8; nt++)
            #pragma unroll
            for (int q = 0; q < 4; q++) acc[mt][nt][q] = 0.0f;

    // A gmem coords: 2 float4 per thread covering [64][32] floats
    const int ar0 = tid >> 3;                 // row 0..31
    const int aq0 = tid & 7;
    const int ar1 = (tid + 256) >> 3;         // row 32..63
    const int aq1 = aq0;

    // --- prefetch chunk 0 ---
    const float* Aseg = A0;
    float4 pa0 = *(const float4*)(Aseg + (size_t)(m0 + ar0) * CDIM + aq0 * 4);
    float4 pa1 = *(const float4*)(Aseg + (size_t)(m0 + ar1) * CDIM + aq1 * 4);
    {
        uint32_t st = sb + A_SZ;              // stage 0
        #pragma unroll
        for (int h = 0; h < 2; h++) {
            const __nv_bfloat16* gw = h ? g_W_lo : g_W_hi;
            #pragma unroll
            for (int i = 0; i < 4; i++) {
                int idx = tid + 256 * i;      // 0..1023
                int row = idx >> 5;           // 0..31
                int q   = idx & 31;           // 16B chunk within 512B row
                cp16(st + h * B_HSZ + row * B_ROWB + q * 16,
                     gw + (size_t)row * 256 + q * 8);
            }
        }
        asm volatile("cp.async.commit_group;" ::: "memory");
    }

    for (int c = 0; c < 24; c++) {
        const int s = c & 1;
        const uint32_t sbB = sb + A_SZ + s * B_STG;

        asm volatile("cp.async.wait_group 0;" ::: "memory");
        __syncthreads();

        // ---- store prefetched A (convert fp32 -> bf16 hi/lo) ----
        {
            float4 x;
            int row, q;
            #pragma unroll
            for (int p = 0; p < 2; p++) {
                if (p == 0) { x = pa0; row = ar0; q = aq0; }
                else        { x = pa1; row = ar1; q = aq1; }
                __nv_bfloat16 h0 = __float2bfloat16(x.x), h1 = __float2bfloat16(x.y);
                __nv_bfloat16 h2 = __float2bfloat16(x.z), h3 = __float2bfloat16(x.w);
                __nv_bfloat16 l0 = __float2bfloat16(x.x - __bfloat162float(h0));
                __nv_bfloat16 l1 = __float2bfloat16(x.y - __bfloat162float(h1));
                __nv_bfloat16 l2 = __float2bfloat16(x.z - __bfloat162float(h2));
                __nv_bfloat16 l3 = __float2bfloat16(x.w - __bfloat162float(h3));
                uint32_t hp0 = ((uint32_t)__bfloat16_as_ushort(h1) << 16) | __bfloat16_as_ushort(h0);
                uint32_t hp1 = ((uint32_t)__bfloat16_as_ushort(h3) << 16) | __bfloat16_as_ushort(h2);
                uint32_t lp0 = ((uint32_t)__bfloat16_as_ushort(l1) << 16) | __bfloat16_as_ushort(l0);
                uint32_t lp1 = ((uint32_t)__bfloat16_as_ushort(l3) << 16) | __bfloat16_as_ushort(l2);
                *(uint2*)(smem + row * A_ROWB + q * 8)         = make_uint2(hp0, hp1);
                *(uint2*)(smem + A_HSZ + row * A_ROWB + q * 8) = make_uint2(lp0, lp1);
            }
        }
        __syncthreads();

        // ---- prefetch chunk c+1 ----
        if (c + 1 < 24) {
            int c1 = c + 1;
            int seg = c1 >> 3;
            Aseg = (seg == 0) ? A0 : (seg == 1) ? (const float*)g_Tx1 : (const float*)g_P2;
            int koff = (c1 & 7) * 32;
            pa0 = *(const float4*)(Aseg + (size_t)(m0 + ar0) * CDIM + koff + aq0 * 4);
            pa1 = *(const float4*)(Aseg + (size_t)(m0 + ar1) * CDIM + koff + aq1 * 4);

            uint32_t st = sb + A_SZ + ((c1 & 1) ? B_STG : 0);
            int kb = c1 * 32;
            #pragma unroll
            for (int h = 0; h < 2; h++) {
                const __nv_bfloat16* gw = h ? g_W_lo : g_W_hi;
                #pragma unroll
                for (int i = 0; i < 4; i++) {
                    int idx = tid + 256 * i;
                    int row = idx >> 5;
                    int q   = idx & 31;
                    cp16(st + h * B_HSZ + row * B_ROWB + q * 16,
                         gw + (size_t)(kb + row) * 256 + q * 8);
                }
            }
            asm volatile("cp.async.commit_group;" ::: "memory");
        }

        // ---- mma over BK=32 (2 k-steps of 16) ----
        #pragma unroll
        for (int k = 0; k < 2; k++) {
            uint32_t ah[2][4], al[2][4];
            #pragma unroll
            for (int mt = 0; mt < 2; mt++) {
                uint32_t arow = (uint32_t)(wm * 32 + mt * 16 + (lane & 15));
                uint32_t aoff = arow * A_ROWB + (uint32_t)(k * 32 + (lane >> 4) * 16);
                ldsm_x4(ah[mt][0], ah[mt][1], ah[mt][2], ah[mt][3], sb + aoff);
                ldsm_x4(al[mt][0], al[mt][1], al[mt][2], al[mt][3], sb + A_HSZ + aoff);
            }
            #pragma unroll
            for (int nt = 0; nt < 8; nt++) {
                uint32_t boff = (uint32_t)(k * 16 + (lane & 15)) * B_ROWB
                              + (uint32_t)(wn * 64 + nt * 8) * 2;
                uint32_t bh0, bh1, bl0, bl1;
                ldsm_x2t(bh0, bh1, sbB + boff);
                ldsm_x2t(bl0, bl1, sbB + B_HSZ + boff);
                #pragma unroll
                for (int mt = 0; mt < 2; mt++) {
                    mma_bf16(acc[mt][nt], ah[mt], bh0, bh1);
                    mma_bf16(acc[mt][nt], ah[mt], bl0, bl1);
                    mma_bf16(acc[mt][nt], al[mt], bh0, bh1);
                }
            }
        }
    }

    // ---- epilogue: acc -> SMEM, then LN per row ----
    __syncthreads();
    float* ep = (float*)(smem + A_SZ);        // [64][256], 64KB (aliases B stages)
    #pragma unroll
    for (int mt = 0; mt < 2; mt++) {
        int r0 = wm * 32 + mt * 16 + (lane >> 2);
        #pragma unroll
        for (int nt = 0; nt < 8; nt++) {
            int cbase = wn * 64 + nt * 8 + (lane & 3) * 2;
            *(float2*)(ep + r0 * 256 + cbase)       = make_float2(acc[mt][nt][0], acc[mt][nt][1]);
            *(float2*)(ep + (r0 + 8) * 256 + cbase) = make_float2(acc[mt][nt][2], acc[mt][nt][3]);
        }
    }
    __syncthreads();

    // warp wid handles rows wid*8..+8; lane covers cols {j*32+lane}
    float bb[8], lw[8], lb[8];
    #pragma unroll
    for (int j = 0; j < 8; j++) {
        int col = j * 32 + lane;
        bb[j] = bias[col]; lw[j] = lnw[col]; lb[j] = lnb[col];
    }
    #pragma unroll
    for (int i = 0; i < 8; i++) {
        int row = wid * 8 + i;
        float v[8];
        float s = 0.0f;
        #pragma unroll
        for (int j = 0; j < 8; j++) {
            v[j] = ep[row * 256 + j * 32 + lane] + bb[j];
            s += v[j];
        }
        #pragma unroll
        for (int o = 16; o > 0; o >>= 1) s += __shfl_xor_sync(0xffffffffu, s, o);
        float mu = s * (1.0f / CDIM);
        float s2 = 0.0f;
        #pragma unroll
        for (int j = 0; j < 8; j++) { float d = v[j] - mu; s2 += d * d; }
        #pragma unroll
        for (int o = 16; o > 0; o >>= 1) s2 += __shfl_xor_sync(0xffffffffu, s2, o);
        float inv = rsqrtf(s2 * (1.0f / CDIM) + 1e-5f);

        size_t rbase = ((size_t)m0 + row) * CDIM;
        #pragma unroll
        for (int j = 0; j < 8; j++)
            out[rbase + j * 32 + lane] = (v[j] - mu) * inv * lw[j] + lb[j];
    }
}

// ---------------- launch -------------------------------------------------------------
extern "C" void kernel_launch(void* const* d_in, const int* in_sizes, int n_in,
                              void* d_out, int out_size) {
    const float* feats = (const float*)d_in[0];      // [B*N, C]
    const float* W     = (const float*)d_in[1];      // [L,K,C,C]
    const float* bpar  = (const float*)d_in[2];      // [L,C]
    const float* lnw   = (const float*)d_in[3];      // [L,C]
    const float* lnb   = (const float*)d_in[4];      // [L,C]
    const int*   ei    = (const int*)d_in[5];        // [2,E] int32 OR int64 (detected)
    float* out = (float*)d_out;

    cudaFuncSetAttribute(k_gemm_mma, cudaFuncAttributeMaxDynamicSharedMemorySize, SMEM_DYN);

    k_zero  <<<(NNODE + 255) / 256, 256>>>();
    k_detect<<<1, 256>>>(ei);
    k_deg   <<<(NEDGE + 255) / 256, 256>>>(ei);
    k_dis   <<<(NNODE + 255) / 256, 256>>>();
    k_scan  <<<1, 1024>>>();
    k_fill  <<<(NEDGE + 255) / 256, 256>>>(ei);
    k_wc    <<<(3 * CDIM * CDIM) / 256, 256>>>(W);
    k_half  <<<(BATCH * NNODE * CDIM / 4) / 256, 256>>>(feats);

    k_prop<<<dim3(NNODE / 8, BATCH), 256>>>(0);   // Tx1 = A_hat @ feats (fp16 gather)
    k_prop<<<dim3(NNODE / 8, BATCH), 256>>>(1);   // P2  = A_hat @ Tx1   (fp16 gather)

    // only layer 1 survives in the reference -> use its params
    k_gemm_mma<<<(BATCH * NNODE) / 64, 256, SMEM_DYN>>>(
        feats, bpar + CDIM, lnw + CDIM, lnb + CDIM, out);
}

// round 12
// speedup vs baseline: 4.1710x; 1.5099x over previous
#include <cuda_runtime.h>
#include <cuda_fp16.h>
#include <cstdint>

// Problem constants (fixed by the reference)
#define BATCH  8
#define NNODE  20000
#define CDIM   256
#define NEDGE  320000

// ---------------- device scratch (allocation-free rule: __device__ globals) ---------
__device__ int   g_hi_nonzero;          // 1 => edge_index buffer is int32
__device__ int   g_deg[NNODE];
__device__ int   g_cnt[NNODE];
__device__ int   g_cursor[NNODE];
__device__ float g_dis[NNODE];
__device__ int   g_rowptr[NNODE + 1];
__device__ int   g_csr_src[NEDGE];
__device__ float g_csr_w[NEDGE];
__device__ __half g_feats16[(size_t)BATCH * NNODE * CDIM]; // 81.9 MB (A seg0 + gather)
__device__ __half g_Tx116  [(size_t)BATCH * NNODE * CDIM]; // 81.9 MB (A seg1 + gather)
__device__ __half g_P216   [(size_t)BATCH * NNODE * CDIM]; // 81.9 MB (A seg2)
// folded layer-1 weights, fp16, [K=768][N=256] row-major
__device__ __half g_W16[768 * 256];

// ---------------- dtype detection ---------------------------------------------------
// Node indices < 20000 -> int64 storage has zero high words everywhere.
__global__ void k_detect(const int* __restrict__ p32) {
    int t = threadIdx.x;
    if (p32[2 * t + 1] != 0) atomicOr(&g_hi_nonzero, 1);
}
__device__ __forceinline__ void load_edge(const int* __restrict__ p, int e, int& s, int& d) {
    if (g_hi_nonzero) { s = p[e];      d = p[NEDGE + e]; }
    else              { s = p[2 * e];  d = p[2 * (NEDGE + e)]; }
}

// ---------------- graph prep kernels ------------------------------------------------
__global__ void k_zero() {
    int i = blockIdx.x * blockDim.x + threadIdx.x;
    if (i < NNODE) { g_deg[i] = 0; g_cnt[i] = 0; g_cursor[i] = 0; }
    if (i == 0) g_hi_nonzero = 0;
}
__global__ void k_deg(const int* __restrict__ ei) {
    int e = blockIdx.x * blockDim.x + threadIdx.x;
    if (e < NEDGE) {
        int s, d; load_edge(ei, e, s, d);
        atomicAdd(&g_deg[s], 1);
        atomicAdd(&g_cnt[d], 1);
    }
}
__global__ void k_dis() {
    int i = blockIdx.x * blockDim.x + threadIdx.x;
    if (i < NNODE) {
        int d = g_deg[i];
        g_dis[i] = (d > 0) ? rsqrtf((float)d) : 0.0f;
    }
}
__global__ void k_scan() {
    __shared__ int sh[1024];
    const int CH = 20;
    int t = threadIdx.x;
    int base = t * CH;
    int sum = 0;
    for (int i = 0; i < CH; i++) { int idx = base + i; if (idx < NNODE) sum += g_cnt[idx]; }
    sh[t] = sum;
    __syncthreads();
    for (int o = 1; o < 1024; o <<= 1) {
        int v = (t >= o) ? sh[t - o] : 0;
        __syncthreads();
        sh[t] += v;
        __syncthreads();
    }
    int run = sh[t] - sum;
    for (int i = 0; i < CH; i++) {
        int idx = base + i;
        if (idx < NNODE) { g_rowptr[idx] = run; run += g_cnt[idx]; }
    }
    if (t == 1023) g_rowptr[NNODE] = sh[1023];
}
__global__ void k_fill(const int* __restrict__ ei) {
    int e = blockIdx.x * blockDim.x + threadIdx.x;
    if (e < NEDGE) {
        int s, d; load_edge(ei, e, s, d);
        float w = -g_dis[s] * g_dis[d];
        int pos = atomicAdd(&g_cursor[d], 1);
        int idx = g_rowptr[d] + pos;
        g_csr_src[idx] = s;
        g_csr_w[idx]   = w;
    }
}

// convert feats fp32 -> fp16 plane
__global__ void k_half(const float* __restrict__ f) {
    size_t i = (size_t)blockIdx.x * blockDim.x + threadIdx.x;   // over elems/4
    float4 x = ((const float4*)f)[i];
    __half2 a = __floats2half2_rn(x.x, x.y);
    __half2 b = __floats2half2_rn(x.z, x.w);
    uint2 p;
    p.x = *(uint32_t*)&a;
    p.y = *(uint32_t*)&b;
    ((uint2*)g_feats16)[i] = p;
}

// fold layer-1 weights into fp16, [K=768][N=256]:
// Wc = [W0-W2 ; W1 ; 2*W2]  (since Tx2 = 2*P2 - Tx0)
__global__ void k_wc(const float* __restrict__ W) {
    int idx = blockIdx.x * blockDim.x + threadIdx.x;   // < 3*256*256, = kg*256 + n
    const int CC = CDIM * CDIM;
    int seg = idx / CC;
    int r   = idx - seg * CC;
    const float* Wl = W + 1 * 3 * CC;  // layer 1
    float v;
    if      (seg == 0) v = Wl[r] - Wl[2 * CC + r];
    else if (seg == 1) v = Wl[CC + r];
    else               v = 2.0f * Wl[2 * CC + r];
    g_W16[idx] = __float2half_rn(v);
}

// ---------------- propagation: Y[b,v,:] = sum_e norm[e] * X[b,src[e],:] ------------
// Warp-per-node, barrier-free, fp16 in/out with fp32 accumulate.
// phase 0: g_feats16 -> g_Tx116.  phase 1: g_Tx116 -> g_P216.
__global__ void __launch_bounds__(256, 8)
k_prop(int phase) {
    const __half* X16 = (phase == 0) ? g_feats16 : g_Tx116;
    __half*       Y16 = (phase == 0) ? g_Tx116 : g_P216;

    int wid  = threadIdx.x >> 5;           // warp in CTA (0..7)
    int lane = threadIdx.x & 31;
    int v    = blockIdx.x * 8 + wid;       // node
    int b    = blockIdx.y;                 // batch

    int start = g_rowptr[v];
    int end   = g_rowptr[v + 1];

    const uint4* X = (const uint4*)(X16 + (size_t)b * NNODE * CDIM);   // 32 uint4/row

    float acc[8];
    #pragma unroll
    for (int j = 0; j < 8; j++) acc[j] = 0.0f;

    #pragma unroll 4
    for (int e = start; e < end; e++) {
        int   s = __ldg(&g_csr_src[e]);     // warp-uniform broadcast
        float w = __ldg(&g_csr_w[e]);
        uint4 raw = X[(size_t)s * 32 + lane];
        float2 f0 = __half22float2(*(__half2*)&raw.x);
        float2 f1 = __half22float2(*(__half2*)&raw.y);
        float2 f2 = __half22float2(*(__half2*)&raw.z);
        float2 f3 = __half22float2(*(__half2*)&raw.w);
        acc[0] += w * f0.x; acc[1] += w * f0.y;
        acc[2] += w * f1.x; acc[3] += w * f1.y;
        acc[4] += w * f2.x; acc[5] += w * f2.y;
        acc[6] += w * f3.x; acc[7] += w * f3.y;
    }

    __half2 o0 = __floats2half2_rn(acc[0], acc[1]);
    __half2 o1 = __floats2half2_rn(acc[2], acc[3]);
    __half2 o2 = __floats2half2_rn(acc[4], acc[5]);
    __half2 o3 = __floats2half2_rn(acc[6], acc[7]);
    uint4 p;
    p.x = *(uint32_t*)&o0; p.y = *(uint32_t*)&o1;
    p.z = *(uint32_t*)&o2; p.w = *(uint32_t*)&o3;
    ((uint4*)(Y16 + (size_t)b * NNODE * CDIM))[(size_t)v * 32 + lane] = p;
}

// ---------------- mma.sync helpers ----------------------------------------------------
__device__ __forceinline__ uint32_t smem_u32(const void* p) {
    uint32_t a;
    asm("{ .reg .u64 t; cvta.to.shared.u64 t, %1; cvt.u32.u64 %0, t; }" : "=r"(a) : "l"(p));
    return a;
}
__device__ __forceinline__ void ldsm_x4(uint32_t& r0, uint32_t& r1, uint32_t& r2, uint32_t& r3,
                                        uint32_t addr) {
    asm volatile("ldmatrix.sync.aligned.m8n8.x4.shared.b16 {%0,%1,%2,%3}, [%4];"
                 : "=r"(r0), "=r"(r1), "=r"(r2), "=r"(r3) : "r"(addr));
}
__device__ __forceinline__ void ldsm_x2t(uint32_t& r0, uint32_t& r1, uint32_t addr) {
    asm volatile("ldmatrix.sync.aligned.m8n8.x2.trans.shared.b16 {%0,%1}, [%2];"
                 : "=r"(r0), "=r"(r1) : "r"(addr));
}
__device__ __forceinline__ void mma_f16(float* c, const uint32_t* a, uint32_t b0, uint32_t b1) {
    asm volatile("mma.sync.aligned.m16n8k16.row.col.f32.f16.f16.f32 "
                 "{%0,%1,%2,%3}, {%4,%5,%6,%7}, {%8,%9}, {%0,%1,%2,%3};"
                 : "+f"(c[0]), "+f"(c[1]), "+f"(c[2]), "+f"(c[3])
                 : "r"(a[0]), "r"(a[1]), "r"(a[2]), "r"(a[3]), "r"(b0), "r"(b1));
}
__device__ __forceinline__ void cp16(uint32_t dst, const void* src) {
    asm volatile("{ .reg .u64 g; cvta.to.global.u64 g, %1;\n\t"
                 "cp.async.ca.shared.global [%0], [g], 16; }" :: "r"(dst), "l"(src));
}

// ---------------- GEMM (mma.sync fp16) + bias + LayerNorm ----------------------------
// out[160000,256] = [Tx0|Tx1|P2]_fp16 (M x 768) @ W16 + b, then row LN.
// CTA: M=64, N=256, BK=32. 8 warps = 2(M) x 4(N); warp tile 32 x 64.
// A and B both double-buffered via cp.async (2 groups in flight).
#define A_ROWB  80                     // 32 fp16 = 64B + 16B pad
#define A_STG   (64 * A_ROWB)          // 5120
#define B_ROWB  528                    // 256 fp16 = 512B + 16B pad
#define B_STG   (32 * B_ROWB)          // 16896
#define OFF_A(s) ((s) * A_STG)                 // 0 / 5120
#define OFF_B(s) (2 * A_STG + (s) * B_STG)     // 10240 / 27136
#define SMEM_DYN 65536                 // also fits the [64][256] f32 epilogue

__global__ void __launch_bounds__(256, 2)
k_gemm_mma(const float* __restrict__ bias,
           const float* __restrict__ lnw,
           const float* __restrict__ lnb,
           float* __restrict__ out)
{
    extern __shared__ char smem[];
    const uint32_t sb = smem_u32(smem);
    const int tid  = threadIdx.x;
    const int wid  = tid >> 5;
    const int lane = tid & 31;
    const int wm   = wid >> 2;          // 0..1 (M)
    const int wn   = wid & 3;           // 0..3 (N)
    const int m0   = blockIdx.x * 64;

    float acc[2][8][4];
    #pragma unroll
    for (int mt = 0; mt < 2; mt++)
        #pragma unroll
        for (int nt = 0; nt < 8; nt++)
            #pragma unroll
            for (int q = 0; q < 4; q++) acc[mt][nt][q] = 0.0f;

    // A: 256 x 16B chunks cover [64][32] fp16; thread t -> row=t>>2, q=t&3
    const int arow = tid >> 2;
    const int aq   = tid & 3;

    // prefetch helper (A chunk c from segment plane + B chunk)
    auto prefetch = [&](int c, int s) {
        int seg  = c >> 3;
        const __half* Aseg = (seg == 0) ? g_feats16 : (seg == 1) ? g_Tx116 : g_P216;
        int koff = (c & 7) * 32;
        cp16(sb + OFF_A(s) + arow * A_ROWB + aq * 16,
             Aseg + (size_t)(m0 + arow) * CDIM + koff + aq * 8);
        int kb = c * 32;
        #pragma unroll
        for (int i = 0; i < 4; i++) {
            int idx = tid + 256 * i;       // 0..1023
            int row = idx >> 5;            // 0..31
            int q   = idx & 31;            // 16B chunk in 512B row
            cp16(sb + OFF_B(s) + row * B_ROWB + q * 16,
                 g_W16 + (size_t)(kb + row) * 256 + q * 8);
        }
        asm volatile("cp.async.commit_group;" ::: "memory");
    };

    prefetch(0, 0);

    for (int c = 0; c < 24; c++) {
        const int s = c & 1;

        __syncthreads();                   // reads of stage s^1 (prev compute) done
        if (c + 1 < 24) {
            prefetch(c + 1, s ^ 1);
            asm volatile("cp.async.wait_group 1;" ::: "memory");   // chunk c ready
        } else {
            asm volatile("cp.async.wait_group 0;" ::: "memory");
        }
        __syncthreads();                   // stage s visible to all

        #pragma unroll
        for (int k = 0; k < 2; k++) {
            uint32_t af[2][4];
            #pragma unroll
            for (int mt = 0; mt < 2; mt++) {
                uint32_t ar = (uint32_t)(wm * 32 + mt * 16 + (lane & 15));
                uint32_t aoff = OFF_A(s) + ar * A_ROWB + (uint32_t)(k * 32 + (lane >> 4) * 16);
                ldsm_x4(af[mt][0], af[mt][1], af[mt][2], af[mt][3], sb + aoff);
            }
            #pragma unroll
            for (int nt = 0; nt < 8; nt++) {
                uint32_t boff = OFF_B(s) + (uint32_t)(k * 16 + (lane & 15)) * B_ROWB
                              + (uint32_t)(wn * 64 + nt * 8) * 2;
                uint32_t b0, b1;
                ldsm_x2t(b0, b1, sb + boff);
                #pragma unroll
                for (int mt = 0; mt < 2; mt++)
                    mma_f16(acc[mt][nt], af[mt], b0, b1);
            }
        }
    }

    // ---- epilogue: acc -> SMEM, then LN per row ----
    __syncthreads();
    float* ep = (float*)smem;                 // [64][256] f32 = 64KB
    #pragma unroll
    for (int mt = 0; mt < 2; mt++) {
        int r0 = wm * 32 + mt * 16 + (lane >> 2);
        #pragma unroll
        for (int nt = 0; nt < 8; nt++) {
            int cbase = wn * 64 + nt * 8 + (lane & 3) * 2;
            *(float2*)(ep + r0 * 256 + cbase)       = make_float2(acc[mt][nt][0], acc[mt][nt][1]);
            *(float2*)(ep + (r0 + 8) * 256 + cbase) = make_float2(acc[mt][nt][2], acc[mt][nt][3]);
        }
    }
    __syncthreads();

    // warp wid handles rows wid*8..+8; lane covers cols {j*32+lane}
    float bb[8], lw[8], lb[8];
    #pragma unroll
    for (int j = 0; j < 8; j++) {
        int col = j * 32 + lane;
        bb[j] = bias[col]; lw[j] = lnw[col]; lb[j] = lnb[col];
    }
    #pragma unroll
    for (int i = 0; i < 8; i++) {
        int row = wid * 8 + i;
        float v[8];
        float ssum = 0.0f;
        #pragma unroll
        for (int j = 0; j < 8; j++) {
            v[j] = ep[row * 256 + j * 32 + lane] + bb[j];
            ssum += v[j];
        }
        #pragma unroll
        for (int o = 16; o > 0; o >>= 1) ssum += __shfl_xor_sync(0xffffffffu, ssum, o);
        float mu = ssum * (1.0f / CDIM);
        float s2 = 0.0f;
        #pragma unroll
        for (int j = 0; j < 8; j++) { float d = v[j] - mu; s2 += d * d; }
        #pragma unroll
        for (int o = 16; o > 0; o >>= 1) s2 += __shfl_xor_sync(0xffffffffu, s2, o);
        float inv = rsqrtf(s2 * (1.0f / CDIM) + 1e-5f);

        size_t rbase = ((size_t)m0 + row) * CDIM;
        #pragma unroll
        for (int j = 0; j < 8; j++)
            out[rbase + j * 32 + lane] = (v[j] - mu) * inv * lw[j] + lb[j];
    }
}

// ---------------- launch -------------------------------------------------------------
extern "C" void kernel_launch(void* const* d_in, const int* in_sizes, int n_in,
                              void* d_out, int out_size) {
    const float* feats = (const float*)d_in[0];      // [B*N, C]
    const float* W     = (const float*)d_in[1];      // [L,K,C,C]
    const float* bpar  = (const float*)d_in[2];      // [L,C]
    const float* lnw   = (const float*)d_in[3];      // [L,C]
    const float* lnb   = (const float*)d_in[4];      // [L,C]
    const int*   ei    = (const int*)d_in[5];        // [2,E] int32 OR int64 (detected)
    float* out = (float*)d_out;

    cudaFuncSetAttribute(k_gemm_mma, cudaFuncAttributeMaxDynamicSharedMemorySize, SMEM_DYN);

    k_zero  <<<(NNODE + 255) / 256, 256>>>();
    k_detect<<<1, 256>>>(ei);
    k_deg   <<<(NEDGE + 255) / 256, 256>>>(ei);
    k_dis   <<<(NNODE + 255) / 256, 256>>>();
    k_scan  <<<1, 1024>>>();
    k_fill  <<<(NEDGE + 255) / 256, 256>>>(ei);
    k_wc    <<<(3 * CDIM * CDIM) / 256, 256>>>(W);
    k_half  <<<(BATCH * NNODE * CDIM / 4) / 256, 256>>>(feats);

    k_prop<<<dim3(NNODE / 8, BATCH), 256>>>(0);   // Tx1 = A_hat @ feats
    k_prop<<<dim3(NNODE / 8, BATCH), 256>>>(1);   // P2  = A_hat @ Tx1

    // only layer 1 survives in the reference -> use its params
    k_gemm_mma<<<(BATCH * NNODE) / 64, 256, SMEM_DYN>>>(
        bpar + CDIM, lnw + CDIM, lnb + CDIM, out);
}